// round 11
// baseline (speedup 1.0000x reference)
#include <cuda_runtime.h>
#include <cuda_fp16.h>
#include <cstdint>
#include <cstddef>

#define NB   32
#define HWD  56
#define CIN  128
#define OC   256
#define NTILE 25088                 // 32 * 28 * 28 output 2x2 tiles
#define NTK  ((size_t)NTILE * 128)  // elements per position plane of U

// scratch (no runtime allocation allowed)
__device__ __align__(16) __half g_u[(size_t)16 * NTILE * 128]; // U[pos][tile*128+c]
__device__ __align__(16) __half g_v[(size_t)16 * OC * 128];    // V[pos][oc*128+c]

__device__ __forceinline__ uint32_t smem_u32(const void* p) {
    uint32_t a;
    asm("{ .reg .u64 t; cvta.to.shared.u64 t, %1; cvt.u32.u64 %0, t; }"
        : "=r"(a) : "l"(p));
    return a;
}
#define CPA16(dst, src) \
    asm volatile("cp.async.cg.shared.global [%0], [%1], 16;" \
                 :: "r"(dst), "l"(src))
#define CPA_COMMIT() asm volatile("cp.async.commit_group;")

__device__ __forceinline__ void ldsm4(uint32_t& r0, uint32_t& r1, uint32_t& r2,
                                      uint32_t& r3, uint32_t addr) {
    asm volatile("ldmatrix.sync.aligned.m8n8.x4.shared.b16 {%0,%1,%2,%3}, [%4];"
                 : "=r"(r0), "=r"(r1), "=r"(r2), "=r"(r3) : "r"(addr));
}

// ---------------------------------------------------------------------------
// Weight transform: V = G g G^T per (oc, c). Exact multiples of 1/4, |V|<512.
// ---------------------------------------------------------------------------
__global__ void wino_wv(const float* __restrict__ wt) {
    int t = blockIdx.x * 256 + threadIdx.x;   // 32768 = 256 oc * 128 c
    if (t >= OC * CIN) return;
    const float* gp = wt + (size_t)t * 9;
    float g[3][3];
#pragma unroll
    for (int r = 0; r < 3; r++)
#pragma unroll
        for (int s = 0; s < 3; s++)
            g[r][s] = (float)(int)gp[r * 3 + s];   // trunc == jnp.trunc

    float tw[4][3];
#pragma unroll
    for (int s = 0; s < 3; s++) {
        tw[0][s] = g[0][s];
        tw[1][s] = 0.5f * (g[0][s] + g[1][s] + g[2][s]);
        tw[2][s] = 0.5f * (g[0][s] - g[1][s] + g[2][s]);
        tw[3][s] = g[2][s];
    }
#pragma unroll
    for (int i = 0; i < 4; i++) {
        float v0 = tw[i][0];
        float v1 = 0.5f * (tw[i][0] + tw[i][1] + tw[i][2]);
        float v2 = 0.5f * (tw[i][0] - tw[i][1] + tw[i][2]);
        float v3 = tw[i][2];
        g_v[(size_t)(i * 4 + 0) * (OC * 128) + t] = __float2half_rn(v0);
        g_v[(size_t)(i * 4 + 1) * (OC * 128) + t] = __float2half_rn(v1);
        g_v[(size_t)(i * 4 + 2) * (OC * 128) + t] = __float2half_rn(v2);
        g_v[(size_t)(i * 4 + 3) * (OC * 128) + t] = __float2half_rn(v3);
    }
}

// ---------------------------------------------------------------------------
// Input transform: U = B^T d B per (tile, c). Integers |U| <= 508, exact fp16.
// One block per (n, ty): loads 128ch x 4row x 56col patch strip as int8.
// ---------------------------------------------------------------------------
__global__ void wino_in(const float* __restrict__ x) {
    __shared__ signed char d8[128 * 228];   // [c]: pitch 228 = 4 rows * 57
    const int tid = threadIdx.x;
    const int n = blockIdx.x / 28, ty = blockIdx.x - n * 28;
    const int gy0 = 2 * ty - 1;

    for (int i = tid; i < 128 * 4 * 56; i += 256) {
        int c = i / 224, r2 = i - c * 224;
        int rr = r2 / 56, xx = r2 - rr * 56;
        int gy = gy0 + rr;
        float v = ((unsigned)gy < 56u)
                  ? x[(((size_t)n * CIN + c) * 56 + gy) * 56 + xx] : 0.0f;
        d8[c * 228 + rr * 57 + xx] = (signed char)(int)v;  // trunc
    }
    __syncthreads();

    for (int it = tid; it < 28 * 128; it += 256) {
        int tx = it >> 7, c = it & 127;
        int x0 = 2 * tx - 1;
        int d[4][4];
#pragma unroll
        for (int r = 0; r < 4; r++)
#pragma unroll
            for (int s = 0; s < 4; s++) {
                int gx = x0 + s;
                d[r][s] = ((unsigned)gx < 56u) ? (int)d8[c * 228 + r * 57 + gx] : 0;
            }
        int td[4][4];
#pragma unroll
        for (int s = 0; s < 4; s++) {
            td[0][s] = d[0][s] - d[2][s];
            td[1][s] = d[1][s] + d[2][s];
            td[2][s] = d[2][s] - d[1][s];
            td[3][s] = d[1][s] - d[3][s];
        }
        int tile = (n * 28 + ty) * 28 + tx;
        __half* up = g_u + (size_t)tile * 128 + c;
#pragma unroll
        for (int i = 0; i < 4; i++) {
            int u0 = td[i][0] - td[i][2];
            int u1 = td[i][1] + td[i][2];
            int u2 = td[i][2] - td[i][1];
            int u3 = td[i][1] - td[i][3];
            up[(size_t)(i * 4 + 0) * NTK] = __float2half_rn((float)u0);
            up[(size_t)(i * 4 + 1) * NTK] = __float2half_rn((float)u1);
            up[(size_t)(i * 4 + 2) * NTK] = __float2half_rn((float)u2);
            up[(size_t)(i * 4 + 3) * NTK] = __float2half_rn((float)u3);
        }
    }
}

// ---------------------------------------------------------------------------
// Winograd GEMM: 16 positions, CTA = 32 tiles x 64 oc, K=128 as 8 k16 stages.
// 512 threads = 16 warps; warp w computes position w (M32 x N64 x K128).
// 3-buffer cp.async; fused output transform + requant epilogue.
// ---------------------------------------------------------------------------
#define A_SZ   16384                 // 16 pos * 32 tiles * 32B
#define B_SZ   32768                 // 16 pos * 64 oc * 32B
#define STG_SZ (A_SZ + B_SZ)         // 49152
#define SMEM_TOTAL (3 * STG_SZ)      // 147456
#define EPITCH 68                    // epilogue smem floats per tile row

__global__ void __launch_bounds__(512, 1) wino_gemm(
    const float* __restrict__ bias, const int* __restrict__ Aq,
    const int* __restrict__ Nq, const int* __restrict__ pmin,
    const int* __restrict__ pmax, float* __restrict__ out)
{
    extern __shared__ __align__(128) char smem[];
    const uint32_t sb = smem_u32(smem);

    const int tid  = threadIdx.x;
    const int lane = tid & 31, wid = tid >> 5;          // wid == position
    const int gid  = lane >> 2, tg = lane & 3;
    const int lrow = lane & 15, lhi = lane >> 4;
    const int oc0   = blockIdx.x * 64;
    const int tile0 = blockIdx.y * 32;

    // ---- loader mapping: 3072 x 16B chunks per stage, 6 per thread ----
    uint32_t dsto[6];
    const __half* srcp[6];
#pragma unroll
    for (int j = 0; j < 6; j++) {
        int cid = j * 512 + tid;
        if (cid < 1024) {            // A: id = pos*64 + tile*2 + kh
            int pos = cid >> 6, rem = cid & 63;
            int tl = rem >> 1, kh = rem & 1;
            dsto[j] = (uint32_t)(pos * 1024 + kh * 512 + tl * 16);
            srcp[j] = g_u + (size_t)pos * NTK + (size_t)(tile0 + tl) * 128 + kh * 8;
        } else {                     // B: id = pos*128 + oc*2 + kh
            int c2 = cid - 1024;
            int pos = c2 >> 7, rem = c2 & 127;
            int oc = rem >> 1, kh = rem & 1;
            dsto[j] = (uint32_t)(A_SZ + pos * 2048 + kh * 1024 + oc * 16);
            srcp[j] = g_v + (size_t)pos * (OC * 128) + (size_t)(oc0 + oc) * 128 + kh * 8;
        }
    }
    auto load_stage = [&](int buf, int ks) {
        const uint32_t d0 = sb + buf * STG_SZ;
#pragma unroll
        for (int j = 0; j < 6; j++)
            CPA16(d0 + dsto[j], srcp[j] + ks * 16);
    };

    float acc[2][8][4];
#pragma unroll
    for (int a = 0; a < 2; a++)
#pragma unroll
        for (int b = 0; b < 8; b++)
#pragma unroll
            for (int c = 0; c < 4; c++) acc[a][b][c] = 0.0f;

    load_stage(0, 0); CPA_COMMIT();
    load_stage(1, 1); CPA_COMMIT();

    for (int ks = 0; ks < 8; ks++) {
        const int buf = ks % 3;
        asm volatile("cp.async.wait_group 1;");
        __syncthreads();

        if (ks + 2 < 8) { load_stage((ks + 2) % 3, ks + 2); }
        CPA_COMMIT();

        const uint32_t Ab = sb + buf * STG_SZ + wid * 1024;
        const uint32_t Bb = sb + buf * STG_SZ + A_SZ + wid * 2048;

        uint32_t bf[8][2];
#pragma unroll
        for (int bt = 0; bt < 4; bt++) {
            uint32_t addr = Bb + (uint32_t)lhi * 1024 + (uint32_t)(bt * 16 + lrow) * 16;
            ldsm4(bf[bt * 2][0], bf[bt * 2 + 1][0],
                  bf[bt * 2][1], bf[bt * 2 + 1][1], addr);
        }
#pragma unroll
        for (int mt = 0; mt < 2; mt++) {
            uint32_t addr = Ab + (uint32_t)lhi * 512 + (uint32_t)(mt * 16 + lrow) * 16;
            uint32_t a0, a1, a2, a3;
            ldsm4(a0, a1, a2, a3, addr);
#pragma unroll
            for (int nt = 0; nt < 8; nt++) {
                asm volatile(
                    "mma.sync.aligned.m16n8k16.row.col.f32.f16.f16.f32 "
                    "{%0,%1,%2,%3}, {%4,%5,%6,%7}, {%8,%9}, {%0,%1,%2,%3};\n"
                    : "+f"(acc[mt][nt][0]), "+f"(acc[mt][nt][1]),
                      "+f"(acc[mt][nt][2]), "+f"(acc[mt][nt][3])
                    : "r"(a0), "r"(a1), "r"(a2), "r"(a3),
                      "r"(bf[nt][0]), "r"(bf[nt][1]));
            }
        }
        __syncthreads();
    }

    // ---- epilogue: inverse transform A^T M A + bias + requant + clip ----
    const int omin = *pmin, omax = *pmax;
    const float fmin = (float)omin, fmax = (float)omax;
    float* smf = (float*)smem;      // [pos][tile16 * EPITCH + oc64]

    for (int chunk = 0; chunk < 2; chunk++) {
        __syncthreads();
        // scatter this chunk's accumulators: tiles chunk*16 .. +15
#pragma unroll
        for (int nt = 0; nt < 8; nt++)
#pragma unroll
            for (int q = 0; q < 4; q++) {
                int tl = gid + 8 * (q >> 1);
                int oc = nt * 8 + tg * 2 + (q & 1);
                smf[wid * (16 * EPITCH) + tl * EPITCH + oc] = acc[chunk][nt][q];
            }
        __syncthreads();

#pragma unroll
        for (int ii = 0; ii < 2; ii++) {
            int item = ii * 512 + tid;          // 1024 = 64 oc * 16 tiles
            int oc_l = item >> 4, tl = item & 15;
            int Tg = tile0 + chunk * 16 + tl;
            int n = Tg / 784, r = Tg - n * 784;
            int tyy = r / 28, txx = r - tyy * 28;
            int oc = oc0 + oc_l;

            float m[16];
#pragma unroll
            for (int p = 0; p < 16; p++)
                m[p] = smf[p * (16 * EPITCH) + tl * EPITCH + oc_l];

            float tm0[4], tm1[4];
#pragma unroll
            for (int v = 0; v < 4; v++) {
                tm0[v] = m[v] + m[4 + v] + m[8 + v];
                tm1[v] = m[4 + v] - m[8 + v] - m[12 + v];
            }
            float Y00 = tm0[0] + tm0[1] + tm0[2];
            float Y01 = tm0[1] - tm0[2] - tm0[3];
            float Y10 = tm1[0] + tm1[1] + tm1[2];
            float Y11 = tm1[1] - tm1[2] - tm1[3];

            float bv = __ldg(&bias[oc]);
            float sc = ldexpf((float)__ldg(&Aq[oc]), -__ldg(&Nq[oc]));
            float f00 = (Y00 + bv) * sc, f01 = (Y01 + bv) * sc;
            float f10 = (Y10 + bv) * sc, f11 = (Y11 + bv) * sc;
            if (omin >= 0) {
                f00 = fminf(fmaxf(rintf(f00), fmin), fmax);
                f01 = fminf(fmaxf(rintf(f01), fmin), fmax);
                f10 = fminf(fmaxf(rintf(f10), fmin), fmax);
                f11 = fminf(fmaxf(rintf(f11), fmin), fmax);
            }
            float* ob = out + (((size_t)n * OC + oc) * 56 + 2 * tyy) * 56 + 2 * txx;
            ob[0] = f00; ob[1] = f01;
            ob[56] = f10; ob[57] = f11;
        }
    }
}

// ---------------------------------------------------------------------------
// Launch. Inputs: x, weight_int, bias_int, A, N, out_min, out_max
// ---------------------------------------------------------------------------
extern "C" void kernel_launch(void* const* d_in, const int* in_sizes, int n_in,
                              void* d_out, int out_size) {
    const float* x    = (const float*)d_in[0];
    const float* wt   = (const float*)d_in[1];
    const float* bias = (const float*)d_in[2];
    const int*   Aq   = (const int*)d_in[3];
    const int*   Nq   = (const int*)d_in[4];
    const int*   omin = (const int*)d_in[5];
    const int*   omax = (const int*)d_in[6];
    float* out = (float*)d_out;

    static int configured = 0;
    if (!configured) {
        cudaFuncSetAttribute(wino_gemm, cudaFuncAttributeMaxDynamicSharedMemorySize,
                             SMEM_TOTAL);
        configured = 1;
    }

    wino_wv<<<(OC * CIN + 255) / 256, 256>>>(wt);
    wino_in<<<NB * 28, 256>>>(x);
    dim3 grid(OC / 64, NTILE / 32);   // oc-split inner => U reuse in L2
    wino_gemm<<<grid, 512, SMEM_TOTAL>>>(bias, Aq, Nq, omin, omax, out);
}